// round 15
// baseline (speedup 1.0000x reference)
#include <cuda_runtime.h>
#include <cuda_bf16.h>

#define Bsz 512
#define Ssz 140
#define Hsz 512
#define Esz 256
#define Vsz 1000
#define Tsz 21
#define NDAYS 7
#define DLEN 20
#define H3 (3*Hsz)
#define SOS 2
#define NB 2048    // width of [Wa | W_hh^T]
#define BM 128     // CTA tile M
#define BN 64      // CTA tile N
#define SMPA 136   // As row stride (conflict-free mma fragment loads)
#define SMPB 72    // Bs row stride
#define GEMM_SMEM (2*16*(SMPA+SMPB)*4)   // 26624 bytes

// ---------------- device scratch (allocation-free) ----------------
__device__ float g_h[2*Bsz*Hsz];            // double-buffered hidden state
__device__ float g_vgh[2*Bsz*NB];           // [v|gh] split-K partials (2 slices)
__device__ float g_EW[Vsz*H3];              // emb @ W_ih^T + b_ih
__device__ float g_BigB[Hsz*NB];            // [Wa | W_hh^T]
__device__ float g_P[4*Bsz*Hsz];            // proj split-K partials (4 slices)
__device__ float g_Pfc[4*Bsz*1024];         // fc split-K partials (4 slices)
__device__ int   g_idx[Tsz*Bsz];            // embedding row per (t,b)
__device__ float g_week[Bsz*NDAYS*Hsz];     // day contexts
__device__ float g_cc[Bsz*2*Hsz];           // [h_new, ctx]
__device__ float g_proj[Bsz*Hsz];           // tanh(cc @ wa_W^T)
__device__ __nv_bfloat16 g_encbf[(size_t)Bsz*Ssz*Hsz];  // 73.4 MB (L2-resident)

#define VGH_STR ((size_t)Bsz*NB)
#define BH      ((size_t)Bsz*Hsz)

// ---------------- tf32 helpers ----------------
__device__ __forceinline__ float tf32r(float x)
{
    asm("cvt.rna.tf32.f32 %0, %0;" : "+f"(x));
    return x;
}

__device__ __forceinline__ void mma8(float (&d)[4], const unsigned (&a)[4],
                                     unsigned b0, unsigned b1)
{
    asm("mma.sync.aligned.m16n8k8.row.col.f32.tf32.tf32.f32 "
        "{%0,%1,%2,%3},{%4,%5,%6,%7},{%8,%9},{%0,%1,%2,%3};"
        : "+f"(d[0]), "+f"(d[1]), "+f"(d[2]), "+f"(d[3])
        : "r"(a[0]), "r"(a[1]), "r"(a[2]), "r"(a[3]), "r"(b0), "r"(b1));
}

// ---------------- one-time setup kernels ----------------
__global__ void build_idx_kernel(const int* __restrict__ label)
{
    int m = blockIdx.x * blockDim.x + threadIdx.x;
    if (m >= Tsz * Bsz) return;
    int t = m / Bsz, b = m % Bsz;
    g_idx[m] = (t == 0) ? SOS : label[b * (Tsz + 1) + (t - 1)];
}

__global__ void build_bigB_kernel(const float* __restrict__ Wa,
                                  const float* __restrict__ W_hh)
{
    int i = blockIdx.x * blockDim.x + threadIdx.x;
    if (i >= Hsz * NB) return;
    int k = i >> 11, n = i & (NB - 1);
    g_BigB[i] = (n < Hsz) ? Wa[k * Hsz + n]
                          : W_hh[(size_t)(n - Hsz) * Hsz + k];
}

__global__ void conv_bf16_kernel(const float* __restrict__ enc)
{
    size_t i = (size_t)blockIdx.x * blockDim.x + threadIdx.x;
    if (i >= ((size_t)Bsz * Ssz * Hsz) / 2) return;
    float2 f = *(const float2*)(enc + i * 2);
    ((__nv_bfloat162*)g_encbf)[i] = __floats2bfloat162_rn(f.x, f.y);
}

// ---------------- tf32 tensor-core GEMM (device function) ----------------
// 128x64 tile, BK=16, 256 thr = 8 warps in 4(m) x 2(n) grid; warp tile 32x32.
// transB=1: B is [N,K] row-major (C = A*B^T); transB=0: B is [K,N] row-major.
// nz>1: split-K; slice bz writes C + bz*splitStride.
__device__ __forceinline__
void gemm_dev(const float* __restrict__ A, const float* __restrict__ Bm,
              float* __restrict__ C, int M, int N, int K, int transB,
              const float* __restrict__ bias, int ldc, size_t splitStride,
              int bxi, int byi, int bz, int nz, char* smraw)
{
    float (*As)[16][SMPA] = (float (*)[16][SMPA])smraw;
    float (*Bs)[16][SMPB] = (float (*)[16][SMPB])(smraw + 2 * 16 * SMPA * 4);

    int tid = threadIdx.x;
    int bm = byi * BM, bn = bxi * BN;
    int Kh = K / nz;
    int kbase = bz * Kh;
    C += (size_t)bz * splitStride;

    int lane = tid & 31, warp = tid >> 5;             // warp 0..7
    int wm = (warp & 3) * 32, wn = (warp >> 2) * 32;  // 4x2 warp grid
    int gr = lane >> 2, tg = lane & 3;

    int arow = tid >> 2, akc = (tid & 3) << 2;   // A loader (rows arow, arow+64)
    int bkr  = tid >> 4, bnc = (tid & 15) << 2;  // B non-trans loader
    int brow = tid >> 2, bkc = (tid & 3) << 2;   // B trans loader

    const float4 zero4 = make_float4(0.f, 0.f, 0.f, 0.f);
    float4 aR0, aR1, bR;

    // prologue: tile 0 -> buffer 0
    aR0 = (bm + arow < M)      ? *(const float4*)(A + (size_t)(bm + arow) * K + kbase + akc) : zero4;
    aR1 = (bm + arow + 64 < M) ? *(const float4*)(A + (size_t)(bm + arow + 64) * K + kbase + akc) : zero4;
    if (transB)
        bR = (bn + brow < N) ? *(const float4*)(Bm + (size_t)(bn + brow) * K + kbase + bkc) : zero4;
    else
        bR = (bn + bnc < N) ? *(const float4*)(Bm + (size_t)(kbase + bkr) * N + bn + bnc) : zero4;
    As[0][akc + 0][arow] = tf32r(aR0.x); As[0][akc + 1][arow] = tf32r(aR0.y);
    As[0][akc + 2][arow] = tf32r(aR0.z); As[0][akc + 3][arow] = tf32r(aR0.w);
    As[0][akc + 0][arow + 64] = tf32r(aR1.x); As[0][akc + 1][arow + 64] = tf32r(aR1.y);
    As[0][akc + 2][arow + 64] = tf32r(aR1.z); As[0][akc + 3][arow + 64] = tf32r(aR1.w);
    if (transB) {
        Bs[0][bkc + 0][brow] = tf32r(bR.x); Bs[0][bkc + 1][brow] = tf32r(bR.y);
        Bs[0][bkc + 2][brow] = tf32r(bR.z); Bs[0][bkc + 3][brow] = tf32r(bR.w);
    } else {
        Bs[0][bkr][bnc + 0] = tf32r(bR.x); Bs[0][bkr][bnc + 1] = tf32r(bR.y);
        Bs[0][bkr][bnc + 2] = tf32r(bR.z); Bs[0][bkr][bnc + 3] = tf32r(bR.w);
    }
    __syncthreads();

    float acc[2][4][4];
#pragma unroll
    for (int mi = 0; mi < 2; mi++)
#pragma unroll
        for (int ni = 0; ni < 4; ni++)
#pragma unroll
            for (int q = 0; q < 4; q++) acc[mi][ni][q] = 0.f;

    int nt = Kh >> 4;
    for (int kt = 0; kt < nt; kt++) {
        int cur = kt & 1;
        bool more = (kt + 1 < nt);
        if (more) {
            int kp = kbase + ((kt + 1) << 4);
            aR0 = (bm + arow < M)      ? *(const float4*)(A + (size_t)(bm + arow) * K + kp + akc) : zero4;
            aR1 = (bm + arow + 64 < M) ? *(const float4*)(A + (size_t)(bm + arow + 64) * K + kp + akc) : zero4;
            if (transB)
                bR = (bn + brow < N) ? *(const float4*)(Bm + (size_t)(bn + brow) * K + kp + bkc) : zero4;
            else
                bR = (bn + bnc < N) ? *(const float4*)(Bm + (size_t)(kp + bkr) * N + bn + bnc) : zero4;
        }
#pragma unroll
        for (int ks = 0; ks < 2; ks++) {
            int k0 = ks << 3;
            unsigned afr[2][4];
#pragma unroll
            for (int mi = 0; mi < 2; mi++) {
                int rm = wm + mi * 16 + gr;
                afr[mi][0] = __float_as_uint(As[cur][k0 + tg][rm]);
                afr[mi][1] = __float_as_uint(As[cur][k0 + tg][rm + 8]);
                afr[mi][2] = __float_as_uint(As[cur][k0 + tg + 4][rm]);
                afr[mi][3] = __float_as_uint(As[cur][k0 + tg + 4][rm + 8]);
            }
#pragma unroll
            for (int ni = 0; ni < 4; ni++) {
                int cn = wn + ni * 8 + gr;
                unsigned b0 = __float_as_uint(Bs[cur][k0 + tg][cn]);
                unsigned b1 = __float_as_uint(Bs[cur][k0 + tg + 4][cn]);
                mma8(acc[0][ni], afr[0], b0, b1);
                mma8(acc[1][ni], afr[1], b0, b1);
            }
        }
        if (more) {
            int nx = cur ^ 1;
            As[nx][akc + 0][arow] = tf32r(aR0.x); As[nx][akc + 1][arow] = tf32r(aR0.y);
            As[nx][akc + 2][arow] = tf32r(aR0.z); As[nx][akc + 3][arow] = tf32r(aR0.w);
            As[nx][akc + 0][arow + 64] = tf32r(aR1.x); As[nx][akc + 1][arow + 64] = tf32r(aR1.y);
            As[nx][akc + 2][arow + 64] = tf32r(aR1.z); As[nx][akc + 3][arow + 64] = tf32r(aR1.w);
            if (transB) {
                Bs[nx][bkc + 0][brow] = tf32r(bR.x); Bs[nx][bkc + 1][brow] = tf32r(bR.y);
                Bs[nx][bkc + 2][brow] = tf32r(bR.z); Bs[nx][bkc + 3][brow] = tf32r(bR.w);
            } else {
                Bs[nx][bkr][bnc + 0] = tf32r(bR.x); Bs[nx][bkr][bnc + 1] = tf32r(bR.y);
                Bs[nx][bkr][bnc + 2] = tf32r(bR.z); Bs[nx][bkr][bnc + 3] = tf32r(bR.w);
            }
        }
        __syncthreads();
    }

    // epilogue: mma C-fragment layout -> global
#pragma unroll
    for (int mi = 0; mi < 2; mi++) {
        int r0 = bm + wm + mi * 16 + gr;
        int r1 = r0 + 8;
#pragma unroll
        for (int ni = 0; ni < 4; ni++) {
            int c0 = bn + wn + ni * 8 + 2 * tg;
            float bb0 = bias ? bias[min(c0, N - 1)] : 0.f;
            float bb1 = bias ? bias[min(c0 + 1, N - 1)] : 0.f;
            if (r0 < M) {
                if (c0 < N)     C[(size_t)r0 * ldc + c0]     = acc[mi][ni][0] + bb0;
                if (c0 + 1 < N) C[(size_t)r0 * ldc + c0 + 1] = acc[mi][ni][1] + bb1;
            }
            if (r1 < M) {
                if (c0 < N)     C[(size_t)r1 * ldc + c0]     = acc[mi][ni][2] + bb0;
                if (c0 + 1 < N) C[(size_t)r1 * ldc + c0 + 1] = acc[mi][ni][3] + bb1;
            }
        }
    }
}

// standalone GEMM wrapper (setup + proj)
__global__ __launch_bounds__(256)
void tgemm(const float* __restrict__ A, const float* __restrict__ Bm,
           float* __restrict__ C, int M, int N, int K, int transB,
           const float* __restrict__ bias, int ldc, size_t splitStride)
{
    __shared__ __align__(16) char sm[GEMM_SMEM];
    gemm_dev(A, Bm, C, M, N, K, transB, bias, ldc, splitStride,
             blockIdx.x, blockIdx.y, blockIdx.z, gridDim.z, sm);
}

// ---------------- day attention (device fn, smem overlay) ----------------
__device__ __forceinline__
void day_attn_dev(const int* __restrict__ numpairs, int b, int d, char* smraw)
{
    __nv_bfloat16* tile = (__nv_bfloat16*)smraw;               // 20480 B, 16-aligned
    float* sv  = (float*)(smraw + DLEN * Hsz * 2);             // 2048 B
    float* ssc = sv + Hsz;                                     // 80 B
    float* swt = ssc + DLEN;
    int tid = threadIdx.x;

    for (int i = tid; i < Hsz; i += 256)
        sv[i] = g_vgh[(size_t)b * NB + i] + g_vgh[VGH_STR + (size_t)b * NB + i];
    const uint4* ep = (const uint4*)(g_encbf + ((size_t)b * Ssz + d * DLEN) * Hsz);
    uint4* tp = (uint4*)tile;
#pragma unroll
    for (int i = tid; i < DLEN * Hsz * 2 / 16; i += 256) tp[i] = ep[i];
    __syncthreads();

    int warp = tid >> 5, lane = tid & 31;
    const __nv_bfloat162* t2 = (const __nv_bfloat162*)tile;
    for (int s = warp; s < DLEN; s += 8) {
        float p = 0.f;
        for (int hp = lane; hp < Hsz / 2; hp += 32) {
            float2 cv = __bfloat1622float2(t2[s * (Hsz / 2) + hp]);
            p += sv[2 * hp] * cv.x + sv[2 * hp + 1] * cv.y;
        }
#pragma unroll
        for (int o = 16; o > 0; o >>= 1) p += __shfl_xor_sync(0xffffffffu, p, o);
        if (lane == 0) ssc[s] = p;
    }
    __syncthreads();
    if (tid < 32) {
        float val = -1e30f;
        if (tid < DLEN)
            val = (numpairs[b * Ssz + d * DLEN + tid] != 0) ? ssc[tid] : -1e9f;
        float mx = val;
#pragma unroll
        for (int o = 16; o > 0; o >>= 1) mx = fmaxf(mx, __shfl_xor_sync(0xffffffffu, mx, o));
        float e = (tid < DLEN) ? expf(val - mx) : 0.f;
        float sm = e;
#pragma unroll
        for (int o = 16; o > 0; o >>= 1) sm += __shfl_xor_sync(0xffffffffu, sm, o);
        if (tid < DLEN) swt[tid] = e / sm;
    }
    __syncthreads();
    {
        int hp = tid;
        float2 a = make_float2(0.f, 0.f);
#pragma unroll
        for (int s = 0; s < DLEN; s++) {
            float2 cv = __bfloat1622float2(t2[s * (Hsz / 2) + hp]);
            a.x += swt[s] * cv.x;
            a.y += swt[s] * cv.y;
        }
        float* wk = g_week + ((size_t)b * NDAYS + d) * Hsz;
        wk[2 * hp] = a.x;
        wk[2 * hp + 1] = a.y;
    }
}

// ---------------- L1: combine4(t-1) | gates(t) | day_attn(t) ----------------
__global__ __launch_bounds__(256)
void mega1_kernel(const int* __restrict__ numpairs,
                  const float* __restrict__ hcur, float* __restrict__ hnew,
                  const float* __restrict__ b_hh, int t, int doComb, int doDG)
{
    __shared__ __align__(16) char sm[GEMM_SMEM];
    int bid = blockIdx.x, tid = threadIdx.x;

    if (bid < 1024) {           // combine4: proj = tanh(sum of 4 partials)
        if (!doComb) return;
        int i = bid * 256 + tid;
        g_proj[i] = tanhf(g_P[i] + g_P[i + BH] + g_P[i + 2 * BH] + g_P[i + 3 * BH]);
        return;
    }
    bid -= 1024;
    if (bid < 1024) {           // GRU gates
        if (!doDG) return;
        int i = bid * 256 + tid;
        int b = i >> 9, j = i & 511;
        const float* gi = g_EW + (size_t)g_idx[t * Bsz + b] * H3;
        const float* gh0 = g_vgh + (size_t)b * NB + Hsz;
        const float* gh1 = gh0 + VGH_STR;
        float ir = gi[j], iz = gi[j + Hsz], inn = gi[j + 2 * Hsz];
        float hr = gh0[j] + gh1[j] + b_hh[j];
        float hz = gh0[j + Hsz] + gh1[j + Hsz] + b_hh[j + Hsz];
        float hn_ = gh0[j + 2 * Hsz] + gh1[j + 2 * Hsz] + b_hh[j + 2 * Hsz];
        float r = 1.f / (1.f + expf(-(ir + hr)));
        float z = 1.f / (1.f + expf(-(iz + hz)));
        float n = tanhf(inn + r * hn_);
        hnew[i] = (1.f - z) * n + z * hcur[i];
        return;
    }
    bid -= 1024;                // day attention
    if (!doDG) return;
    day_attn_dev(numpairs, bid / NDAYS, bid % NDAYS, sm);
}

// ---------------- L2: fcGEMM(t-1) | BigGEMM(t) ----------------
__global__ __launch_bounds__(256)
void mega2_kernel(const float* __restrict__ hn, const float* __restrict__ fc_W,
                  int doFc, int doBig)
{
    __shared__ __align__(16) char sm[GEMM_SMEM];
    int bid = blockIdx.x;
    if (bid < 256) {            // fc: 16 x-tiles, 4 y-tiles, 4 z
        if (!doFc) return;
        int bz = bid >> 6, rem = bid & 63;
        gemm_dev(g_proj, fc_W, g_Pfc, Bsz, Vsz, Hsz, 1, nullptr, 1024,
                 (size_t)Bsz * 1024, rem & 15, rem >> 4, bz, 4, sm);
        return;
    }
    bid -= 256;                 // BigGEMM: 32 x-tiles, 4 y-tiles, 2 z
    if (!doBig) return;
    int bz = bid >> 7, rem = bid & 127;
    gemm_dev(hn, g_BigB, g_vgh, Bsz, NB, Hsz, 0, nullptr, NB,
             VGH_STR, rem & 31, rem >> 5, bz, 2, sm);
}

// ---------------- L3: fc_softmax(t-1) | week_attn(t) ----------------
__global__ __launch_bounds__(256)
void mega3_kernel(const float* __restrict__ fc_b, float* __restrict__ out,
                  const float* __restrict__ hn, int tOut, int doSm, int doWeek)
{
    __shared__ float sred[8];
    __shared__ float su[Hsz];
    __shared__ float sc[8];
    __shared__ float aw[8];
    int bid = blockIdx.x, tid = threadIdx.x;

    if (bid < 512) {            // fused fc combine4 + bias + log_softmax
        if (!doSm) return;
        int b = bid;
        const size_t FSTR = (size_t)Bsz * 1024;
        const float* P0 = g_Pfc + (size_t)b * 1024;
        float lv[4];
        float mx = -1e30f;
#pragma unroll
        for (int q = 0; q < 4; q++) {
            int i = tid + q * 256;
            float v = -1e30f;
            if (i < Vsz)
                v = P0[i] + P0[i + FSTR] + P0[i + 2 * FSTR] + P0[i + 3 * FSTR] + fc_b[i];
            lv[q] = v;
            mx = fmaxf(mx, v);
        }
#pragma unroll
        for (int o = 16; o > 0; o >>= 1) mx = fmaxf(mx, __shfl_xor_sync(0xffffffffu, mx, o));
        if ((tid & 31) == 0) sred[tid >> 5] = mx;
        __syncthreads();
        if (tid == 0) {
            float m = sred[0];
            for (int i = 1; i < 8; i++) m = fmaxf(m, sred[i]);
            sred[0] = m;
        }
        __syncthreads();
        mx = sred[0];
        __syncthreads();
        float s = 0.f;
#pragma unroll
        for (int q = 0; q < 4; q++)
            if (tid + q * 256 < Vsz) s += expf(lv[q] - mx);
#pragma unroll
        for (int o = 16; o > 0; o >>= 1) s += __shfl_xor_sync(0xffffffffu, s, o);
        if ((tid & 31) == 0) sred[tid >> 5] = s;
        __syncthreads();
        if (tid == 0) {
            float ss = 0.f;
            for (int i = 0; i < 8; i++) ss += sred[i];
            sred[0] = mx + logf(ss);
        }
        __syncthreads();
        float lse = sred[0];
        float* row = out + ((size_t)b * Tsz + tOut) * Vsz;
#pragma unroll
        for (int q = 0; q < 4; q++) {
            int i = tid + q * 256;
            if (i < Vsz) row[i] = lv[q] - lse;
        }
        return;
    }

    // week attention + cc build (256 threads)
    if (!doWeek) return;
    int b = bid - 512;
    for (int i = tid; i < Hsz; i += 256)
        su[i] = g_vgh[(size_t)b * NB + i] + g_vgh[VGH_STR + (size_t)b * NB + i];
    __syncthreads();
    int warp = tid >> 5, lane = tid & 31;
    for (int d = warp; d < NDAYS; d += 8) {
        const float* w = g_week + ((size_t)b * NDAYS + d) * Hsz;
        float p = 0.f;
        for (int h = lane; h < Hsz; h += 32) p += su[h] * w[h];
#pragma unroll
        for (int o = 16; o > 0; o >>= 1) p += __shfl_xor_sync(0xffffffffu, p, o);
        if (lane == 0) sc[d] = p;
    }
    __syncthreads();
    if (tid == 0) {
        float mx = -1e30f;
        for (int d = 0; d < NDAYS; d++) mx = fmaxf(mx, sc[d]);
        float e[NDAYS], s = 0.f;
        for (int d = 0; d < NDAYS; d++) { e[d] = expf(sc[d] - mx); s += e[d]; }
        for (int d = 0; d < NDAYS; d++) aw[d] = e[d] / s;
    }
    __syncthreads();
    for (int h = tid; h < Hsz; h += 256) {
        float c = 0.f;
#pragma unroll
        for (int d = 0; d < NDAYS; d++)
            c += aw[d] * g_week[((size_t)b * NDAYS + d) * Hsz + h];
        g_cc[(size_t)b * 2 * Hsz + Hsz + h] = c;
        g_cc[(size_t)b * 2 * Hsz + h] = hn[b * Hsz + h];
    }
}

__global__ void write_lastin_kernel(const int* __restrict__ label,
                                    float* __restrict__ out)
{
    int b = blockIdx.x * blockDim.x + threadIdx.x;
    if (b < Bsz)
        out[(size_t)Bsz * Tsz * Vsz + b] = (float)label[b * (Tsz + 1) + (Tsz - 1)];
}

// ---------------- host orchestration ----------------
static void launch_gemm(const float* A, const float* Bm, float* C,
                        int M, int N, int K, int transB, const float* bias,
                        int ldc, int splitZ, size_t splitStride)
{
    dim3 grid((N + BN - 1) / BN, (M + BM - 1) / BM, splitZ);
    tgemm<<<grid, 256>>>(A, Bm, C, M, N, K, transB, bias, ldc, splitStride);
}

extern "C" void kernel_launch(void* const* d_in, const int* in_sizes, int n_in,
                              void* d_out, int out_size)
{
    const float* enc_h   = (const float*)d_in[0];
    const float* enc_o   = (const float*)d_in[1];
    const int*   label   = (const int*)d_in[2];
    const int*   numpair = (const int*)d_in[3];
    const float* emb     = (const float*)d_in[4];
    const float* W_ih    = (const float*)d_in[5];
    const float* W_hh    = (const float*)d_in[6];
    const float* b_ih    = (const float*)d_in[7];
    const float* b_hh    = (const float*)d_in[8];
    const float* Wa      = (const float*)d_in[9];
    const float* wa_W    = (const float*)d_in[10];
    const float* fc_W    = (const float*)d_in[11];
    const float* fc_b    = (const float*)d_in[12];
    float* out = (float*)d_out;

    float *p_h, *p_vgh, *p_EW, *p_BigB, *p_P, *p_cc;
    cudaGetSymbolAddress((void**)&p_h,    g_h);
    cudaGetSymbolAddress((void**)&p_vgh,  g_vgh);
    cudaGetSymbolAddress((void**)&p_EW,   g_EW);
    cudaGetSymbolAddress((void**)&p_BigB, g_BigB);
    cudaGetSymbolAddress((void**)&p_P,    g_P);
    cudaGetSymbolAddress((void**)&p_cc,   g_cc);

    // h0 = encoder_hidden[0]
    cudaMemcpyAsync(p_h, enc_h, (size_t)Bsz * Hsz * sizeof(float),
                    cudaMemcpyDeviceToDevice);

    // one-time setup
    build_idx_kernel<<<(Tsz * Bsz + 255) / 256, 256>>>(label);
    build_bigB_kernel<<<(Hsz * NB + 255) / 256, 256>>>(Wa, W_hh);
    conv_bf16_kernel<<<(int)(((size_t)Bsz * Ssz * Hsz / 2 + 255) / 256), 256>>>(enc_o);
    // EW = emb @ W_ih^T + b_ih   [1000 x 1536]
    launch_gemm(emb, W_ih, p_EW, Vsz, H3, Esz, 1, b_ih, H3, 1, 0);

    // initial [v0 | gh0] = h0 @ [Wa | W_hh^T]  (split-K 2)
    launch_gemm(p_h, p_BigB, p_vgh, Bsz, NB, Hsz, 0, nullptr, NB, 2, VGH_STR);

    // pipelined main loop: 4 launches/step
    for (int t = 0; t < Tsz; t++) {
        float* hc = p_h + (size_t)(t & 1) * Bsz * Hsz;
        float* hn = p_h + (size_t)((t + 1) & 1) * Bsz * Hsz;
        int prev = (t > 0) ? 1 : 0;

        // L1: combine4(t-1) | gates(t) | day_attn(t)
        mega1_kernel<<<1024 + 1024 + Bsz * NDAYS, 256>>>(numpair, hc, hn, b_hh,
                                                         t, prev, 1);
        // L2: fcGEMM(t-1) | BigGEMM(t) ([u_t | gh_{t+1}], u_t = v_{t+1})
        mega2_kernel<<<512, 256>>>(hn, fc_W, prev, 1);
        // L3: fc_softmax(t-1) | week_attn(t)
        mega3_kernel<<<1024, 256>>>(fc_b, out, hn, t - 1, prev, 1);
        // L4: projGEMM(t): partials of cc @ wa_W^T (K=1024, split-K 4)
        launch_gemm(p_cc, wa_W, p_P, Bsz, Hsz, 2 * Hsz, 1, nullptr, Hsz,
                    4, BH);
    }

    // epilogue: flush tail of step T-1
    mega1_kernel<<<1024 + 1024 + Bsz * NDAYS, 256>>>(numpair, p_h, p_h, b_hh,
                                                     0, 1, 0);
    mega2_kernel<<<512, 256>>>(p_h, fc_W, 1, 0);
    mega3_kernel<<<1024, 256>>>(fc_b, out, p_h, Tsz - 1, 1, 0);

    if (out_size >= Bsz * Tsz * Vsz + Bsz)
        write_lastin_kernel<<<2, 256>>>(label, out);
}

// round 16
// speedup vs baseline: 1.4563x; 1.4563x over previous
#include <cuda_runtime.h>
#include <cuda_bf16.h>

#define Bsz 512
#define Ssz 140
#define Hsz 512
#define Esz 256
#define Vsz 1000
#define Tsz 21
#define NDAYS 7
#define DLEN 20
#define H3 (3*Hsz)
#define SOS 2
#define NB 2048    // width of [Wa | W_hh^T]
#define BM 128     // CTA tile M
#define BN 64      // CTA tile N
#define SMPA 136   // As row stride (conflict-free mma fragment loads)
#define SMPB 72    // Bs row stride

// ---------------- device scratch (allocation-free) ----------------
__device__ float g_h[2*Bsz*Hsz];            // double-buffered hidden state
__device__ float g_vgh[2*Bsz*NB];           // [v|gh] split-K partials (2 slices)
__device__ float g_EW[Vsz*H3];              // emb @ W_ih^T + b_ih
__device__ float g_BigB[Hsz*NB];            // [Wa | W_hh^T]
__device__ float g_P[4*Bsz*Hsz];            // proj split-K partials (4 slices)
__device__ float g_Pfc[4*Bsz*1024];         // fc split-K partials (4 slices)
__device__ int   g_idx[Tsz*Bsz];            // embedding row per (t,b)
__device__ float g_week[Bsz*NDAYS*Hsz];     // day contexts
__device__ float g_cc[Bsz*2*Hsz];           // [h_new, ctx]
__device__ float g_proj[Bsz*Hsz];           // tanh(cc @ wa_W^T)
__device__ __nv_bfloat16 g_encbf[(size_t)Bsz*Ssz*Hsz];  // 73.4 MB (L2-resident)

#define VGH_STR ((size_t)Bsz*NB)
#define BH      ((size_t)Bsz*Hsz)

// ---------------- tf32 helpers ----------------
__device__ __forceinline__ float tf32r(float x)
{
    asm("cvt.rna.tf32.f32 %0, %0;" : "+f"(x));
    return x;
}

__device__ __forceinline__ void mma8(float (&d)[4], const unsigned (&a)[4],
                                     unsigned b0, unsigned b1)
{
    asm("mma.sync.aligned.m16n8k8.row.col.f32.tf32.tf32.f32 "
        "{%0,%1,%2,%3},{%4,%5,%6,%7},{%8,%9},{%0,%1,%2,%3};"
        : "+f"(d[0]), "+f"(d[1]), "+f"(d[2]), "+f"(d[3])
        : "r"(a[0]), "r"(a[1]), "r"(a[2]), "r"(a[3]), "r"(b0), "r"(b1));
}

// ---------------- one-time setup kernels ----------------
__global__ void build_idx_kernel(const int* __restrict__ label)
{
    int m = blockIdx.x * blockDim.x + threadIdx.x;
    if (m >= Tsz * Bsz) return;
    int t = m / Bsz, b = m % Bsz;
    g_idx[m] = (t == 0) ? SOS : label[b * (Tsz + 1) + (t - 1)];
}

__global__ void build_bigB_kernel(const float* __restrict__ Wa,
                                  const float* __restrict__ W_hh)
{
    int i = blockIdx.x * blockDim.x + threadIdx.x;
    if (i >= Hsz * NB) return;
    int k = i >> 11, n = i & (NB - 1);
    g_BigB[i] = (n < Hsz) ? Wa[k * Hsz + n]
                          : W_hh[(size_t)(n - Hsz) * Hsz + k];
}

__global__ void conv_bf16_kernel(const float* __restrict__ enc)
{
    size_t i = (size_t)blockIdx.x * blockDim.x + threadIdx.x;
    if (i >= ((size_t)Bsz * Ssz * Hsz) / 2) return;
    float2 f = *(const float2*)(enc + i * 2);
    ((__nv_bfloat162*)g_encbf)[i] = __floats2bfloat162_rn(f.x, f.y);
}

// ---------------- tf32 tensor-core GEMM (device function, TYPED smem) ----------------
// 128x64 tile, BK=16, 256 thr = 8 warps in 4(m) x 2(n) grid; warp tile 32x32.
// transB=1: B is [N,K] row-major (C = A*B^T); transB=0: B is [K,N] row-major.
// nz>1: split-K; slice bz writes C + bz*splitStride.
__device__ __forceinline__
void gemm_dev(const float* __restrict__ A, const float* __restrict__ Bm,
              float* __restrict__ C, int M, int N, int K, int transB,
              const float* __restrict__ bias, int ldc, size_t splitStride,
              int bxi, int byi, int bz, int nz,
              float As[2][16][SMPA], float Bs[2][16][SMPB])
{
    int tid = threadIdx.x;
    int bm = byi * BM, bn = bxi * BN;
    int Kh = K / nz;
    int kbase = bz * Kh;
    C += (size_t)bz * splitStride;

    int lane = tid & 31, warp = tid >> 5;             // warp 0..7
    int wm = (warp & 3) * 32, wn = (warp >> 2) * 32;  // 4x2 warp grid
    int gr = lane >> 2, tg = lane & 3;

    int arow = tid >> 2, akc = (tid & 3) << 2;   // A loader (rows arow, arow+64)
    int bkr  = tid >> 4, bnc = (tid & 15) << 2;  // B non-trans loader
    int brow = tid >> 2, bkc = (tid & 3) << 2;   // B trans loader

    const float4 zero4 = make_float4(0.f, 0.f, 0.f, 0.f);
    float4 aR0, aR1, bR;

    // prologue: tile 0 -> buffer 0
    aR0 = (bm + arow < M)      ? *(const float4*)(A + (size_t)(bm + arow) * K + kbase + akc) : zero4;
    aR1 = (bm + arow + 64 < M) ? *(const float4*)(A + (size_t)(bm + arow + 64) * K + kbase + akc) : zero4;
    if (transB)
        bR = (bn + brow < N) ? *(const float4*)(Bm + (size_t)(bn + brow) * K + kbase + bkc) : zero4;
    else
        bR = (bn + bnc < N) ? *(const float4*)(Bm + (size_t)(kbase + bkr) * N + bn + bnc) : zero4;
    As[0][akc + 0][arow] = tf32r(aR0.x); As[0][akc + 1][arow] = tf32r(aR0.y);
    As[0][akc + 2][arow] = tf32r(aR0.z); As[0][akc + 3][arow] = tf32r(aR0.w);
    As[0][akc + 0][arow + 64] = tf32r(aR1.x); As[0][akc + 1][arow + 64] = tf32r(aR1.y);
    As[0][akc + 2][arow + 64] = tf32r(aR1.z); As[0][akc + 3][arow + 64] = tf32r(aR1.w);
    if (transB) {
        Bs[0][bkc + 0][brow] = tf32r(bR.x); Bs[0][bkc + 1][brow] = tf32r(bR.y);
        Bs[0][bkc + 2][brow] = tf32r(bR.z); Bs[0][bkc + 3][brow] = tf32r(bR.w);
    } else {
        Bs[0][bkr][bnc + 0] = tf32r(bR.x); Bs[0][bkr][bnc + 1] = tf32r(bR.y);
        Bs[0][bkr][bnc + 2] = tf32r(bR.z); Bs[0][bkr][bnc + 3] = tf32r(bR.w);
    }
    __syncthreads();

    float acc[2][4][4];
#pragma unroll
    for (int mi = 0; mi < 2; mi++)
#pragma unroll
        for (int ni = 0; ni < 4; ni++)
#pragma unroll
            for (int q = 0; q < 4; q++) acc[mi][ni][q] = 0.f;

    int nt = Kh >> 4;
    for (int kt = 0; kt < nt; kt++) {
        int cur = kt & 1;
        bool more = (kt + 1 < nt);
        if (more) {
            int kp = kbase + ((kt + 1) << 4);
            aR0 = (bm + arow < M)      ? *(const float4*)(A + (size_t)(bm + arow) * K + kp + akc) : zero4;
            aR1 = (bm + arow + 64 < M) ? *(const float4*)(A + (size_t)(bm + arow + 64) * K + kp + akc) : zero4;
            if (transB)
                bR = (bn + brow < N) ? *(const float4*)(Bm + (size_t)(bn + brow) * K + kp + bkc) : zero4;
            else
                bR = (bn + bnc < N) ? *(const float4*)(Bm + (size_t)(kp + bkr) * N + bn + bnc) : zero4;
        }
#pragma unroll
        for (int ks = 0; ks < 2; ks++) {
            int k0 = ks << 3;
            unsigned afr[2][4];
#pragma unroll
            for (int mi = 0; mi < 2; mi++) {
                int rm = wm + mi * 16 + gr;
                afr[mi][0] = __float_as_uint(As[cur][k0 + tg][rm]);
                afr[mi][1] = __float_as_uint(As[cur][k0 + tg][rm + 8]);
                afr[mi][2] = __float_as_uint(As[cur][k0 + tg + 4][rm]);
                afr[mi][3] = __float_as_uint(As[cur][k0 + tg + 4][rm + 8]);
            }
#pragma unroll
            for (int ni = 0; ni < 4; ni++) {
                int cn = wn + ni * 8 + gr;
                unsigned b0 = __float_as_uint(Bs[cur][k0 + tg][cn]);
                unsigned b1 = __float_as_uint(Bs[cur][k0 + tg + 4][cn]);
                mma8(acc[0][ni], afr[0], b0, b1);
                mma8(acc[1][ni], afr[1], b0, b1);
            }
        }
        if (more) {
            int nx = cur ^ 1;
            As[nx][akc + 0][arow] = tf32r(aR0.x); As[nx][akc + 1][arow] = tf32r(aR0.y);
            As[nx][akc + 2][arow] = tf32r(aR0.z); As[nx][akc + 3][arow] = tf32r(aR0.w);
            As[nx][akc + 0][arow + 64] = tf32r(aR1.x); As[nx][akc + 1][arow + 64] = tf32r(aR1.y);
            As[nx][akc + 2][arow + 64] = tf32r(aR1.z); As[nx][akc + 3][arow + 64] = tf32r(aR1.w);
            if (transB) {
                Bs[nx][bkc + 0][brow] = tf32r(bR.x); Bs[nx][bkc + 1][brow] = tf32r(bR.y);
                Bs[nx][bkc + 2][brow] = tf32r(bR.z); Bs[nx][bkc + 3][brow] = tf32r(bR.w);
            } else {
                Bs[nx][bkr][bnc + 0] = tf32r(bR.x); Bs[nx][bkr][bnc + 1] = tf32r(bR.y);
                Bs[nx][bkr][bnc + 2] = tf32r(bR.z); Bs[nx][bkr][bnc + 3] = tf32r(bR.w);
            }
        }
        __syncthreads();
    }

    // epilogue: mma C-fragment layout -> global
#pragma unroll
    for (int mi = 0; mi < 2; mi++) {
        int r0 = bm + wm + mi * 16 + gr;
        int r1 = r0 + 8;
#pragma unroll
        for (int ni = 0; ni < 4; ni++) {
            int c0 = bn + wn + ni * 8 + 2 * tg;
            float bb0 = bias ? bias[min(c0, N - 1)] : 0.f;
            float bb1 = bias ? bias[min(c0 + 1, N - 1)] : 0.f;
            if (r0 < M) {
                if (c0 < N)     C[(size_t)r0 * ldc + c0]     = acc[mi][ni][0] + bb0;
                if (c0 + 1 < N) C[(size_t)r0 * ldc + c0 + 1] = acc[mi][ni][1] + bb1;
            }
            if (r1 < M) {
                if (c0 < N)     C[(size_t)r1 * ldc + c0]     = acc[mi][ni][2] + bb0;
                if (c0 + 1 < N) C[(size_t)r1 * ldc + c0 + 1] = acc[mi][ni][3] + bb1;
            }
        }
    }
}

// standalone GEMM wrapper (setup + proj)
__global__ __launch_bounds__(256)
void tgemm(const float* __restrict__ A, const float* __restrict__ Bm,
           float* __restrict__ C, int M, int N, int K, int transB,
           const float* __restrict__ bias, int ldc, size_t splitStride)
{
    __shared__ float As[2][16][SMPA];
    __shared__ float Bs[2][16][SMPB];
    gemm_dev(A, Bm, C, M, N, K, transB, bias, ldc, splitStride,
             blockIdx.x, blockIdx.y, blockIdx.z, gridDim.z, As, Bs);
}

// ---------------- day attention (device fn, own typed smem) ----------------
__device__ __forceinline__
void day_attn_dev(const int* __restrict__ numpairs, int b, int d)
{
    __shared__ __align__(16) __nv_bfloat16 tile[DLEN * Hsz];   // 20480 B
    __shared__ float sv[Hsz];
    __shared__ float ssc[DLEN];
    __shared__ float swt[DLEN];
    int tid = threadIdx.x;

    for (int i = tid; i < Hsz; i += 256)
        sv[i] = g_vgh[(size_t)b * NB + i] + g_vgh[VGH_STR + (size_t)b * NB + i];
    const uint4* ep = (const uint4*)(g_encbf + ((size_t)b * Ssz + d * DLEN) * Hsz);
    uint4* tp = (uint4*)tile;
#pragma unroll
    for (int i = tid; i < DLEN * Hsz * 2 / 16; i += 256) tp[i] = ep[i];
    __syncthreads();

    int warp = tid >> 5, lane = tid & 31;
    const __nv_bfloat162* t2 = (const __nv_bfloat162*)tile;
    for (int s = warp; s < DLEN; s += 8) {
        float p = 0.f;
        for (int hp = lane; hp < Hsz / 2; hp += 32) {
            float2 cv = __bfloat1622float2(t2[s * (Hsz / 2) + hp]);
            p += sv[2 * hp] * cv.x + sv[2 * hp + 1] * cv.y;
        }
#pragma unroll
        for (int o = 16; o > 0; o >>= 1) p += __shfl_xor_sync(0xffffffffu, p, o);
        if (lane == 0) ssc[s] = p;
    }
    __syncthreads();
    if (tid < 32) {
        float val = -1e30f;
        if (tid < DLEN)
            val = (numpairs[b * Ssz + d * DLEN + tid] != 0) ? ssc[tid] : -1e9f;
        float mx = val;
#pragma unroll
        for (int o = 16; o > 0; o >>= 1) mx = fmaxf(mx, __shfl_xor_sync(0xffffffffu, mx, o));
        float e = (tid < DLEN) ? expf(val - mx) : 0.f;
        float sm = e;
#pragma unroll
        for (int o = 16; o > 0; o >>= 1) sm += __shfl_xor_sync(0xffffffffu, sm, o);
        if (tid < DLEN) swt[tid] = e / sm;
    }
    __syncthreads();
    {
        int hp = tid;
        float2 a = make_float2(0.f, 0.f);
#pragma unroll
        for (int s = 0; s < DLEN; s++) {
            float2 cv = __bfloat1622float2(t2[s * (Hsz / 2) + hp]);
            a.x += swt[s] * cv.x;
            a.y += swt[s] * cv.y;
        }
        float* wk = g_week + ((size_t)b * NDAYS + d) * Hsz;
        wk[2 * hp] = a.x;
        wk[2 * hp + 1] = a.y;
    }
}

// ---------------- L1: combine4(t-1) | gates(t) | day_attn(t) ----------------
__global__ __launch_bounds__(256)
void mega1_kernel(const int* __restrict__ numpairs,
                  const float* __restrict__ hcur, float* __restrict__ hnew,
                  const float* __restrict__ b_hh, int t, int doComb, int doDG)
{
    int bid = blockIdx.x, tid = threadIdx.x;

    if (bid < 1024) {           // combine4: proj = tanh(sum of 4 partials)
        if (!doComb) return;
        int i = bid * 256 + tid;
        g_proj[i] = tanhf(g_P[i] + g_P[i + BH] + g_P[i + 2 * BH] + g_P[i + 3 * BH]);
        return;
    }
    bid -= 1024;
    if (bid < 1024) {           // GRU gates
        if (!doDG) return;
        int i = bid * 256 + tid;
        int b = i >> 9, j = i & 511;
        const float* gi = g_EW + (size_t)g_idx[t * Bsz + b] * H3;
        const float* gh0 = g_vgh + (size_t)b * NB + Hsz;
        const float* gh1 = gh0 + VGH_STR;
        float ir = gi[j], iz = gi[j + Hsz], inn = gi[j + 2 * Hsz];
        float hr = gh0[j] + gh1[j] + b_hh[j];
        float hz = gh0[j + Hsz] + gh1[j + Hsz] + b_hh[j + Hsz];
        float hn_ = gh0[j + 2 * Hsz] + gh1[j + 2 * Hsz] + b_hh[j + 2 * Hsz];
        float r = 1.f / (1.f + expf(-(ir + hr)));
        float z = 1.f / (1.f + expf(-(iz + hz)));
        float n = tanhf(inn + r * hn_);
        hnew[i] = (1.f - z) * n + z * hcur[i];
        return;
    }
    bid -= 1024;                // day attention
    if (!doDG) return;
    day_attn_dev(numpairs, bid / NDAYS, bid % NDAYS);
}

// ---------------- L2: fcGEMM(t-1) | BigGEMM(t) ----------------
__global__ __launch_bounds__(256)
void mega2_kernel(const float* __restrict__ hn, const float* __restrict__ fc_W,
                  int doFc, int doBig)
{
    __shared__ float As[2][16][SMPA];
    __shared__ float Bs[2][16][SMPB];
    int bid = blockIdx.x;
    if (bid < 256) {            // fc: 16 x-tiles, 4 y-tiles, 4 z
        if (!doFc) return;
        int bz = bid >> 6, rem = bid & 63;
        gemm_dev(g_proj, fc_W, g_Pfc, Bsz, Vsz, Hsz, 1, nullptr, 1024,
                 (size_t)Bsz * 1024, rem & 15, rem >> 4, bz, 4, As, Bs);
        return;
    }
    bid -= 256;                 // BigGEMM: 32 x-tiles, 4 y-tiles, 2 z
    if (!doBig) return;
    int bz = bid >> 7, rem = bid & 127;
    gemm_dev(hn, g_BigB, g_vgh, Bsz, NB, Hsz, 0, nullptr, NB,
             VGH_STR, rem & 31, rem >> 5, bz, 2, As, Bs);
}

// ---------------- L3: fc_softmax(t-1) | week_attn(t) ----------------
__global__ __launch_bounds__(256)
void mega3_kernel(const float* __restrict__ fc_b, float* __restrict__ out,
                  const float* __restrict__ hn, int tOut, int doSm, int doWeek)
{
    __shared__ float sred[8];
    __shared__ float su[Hsz];
    __shared__ float sc[8];
    __shared__ float aw[8];
    int bid = blockIdx.x, tid = threadIdx.x;

    if (bid < 512) {            // fused fc combine4 + bias + log_softmax
        if (!doSm) return;
        int b = bid;
        const size_t FSTR = (size_t)Bsz * 1024;
        const float* P0 = g_Pfc + (size_t)b * 1024;
        float lv[4];
        float mx = -1e30f;
#pragma unroll
        for (int q = 0; q < 4; q++) {
            int i = tid + q * 256;
            float v = -1e30f;
            if (i < Vsz)
                v = P0[i] + P0[i + FSTR] + P0[i + 2 * FSTR] + P0[i + 3 * FSTR] + fc_b[i];
            lv[q] = v;
            mx = fmaxf(mx, v);
        }
#pragma unroll
        for (int o = 16; o > 0; o >>= 1) mx = fmaxf(mx, __shfl_xor_sync(0xffffffffu, mx, o));
        if ((tid & 31) == 0) sred[tid >> 5] = mx;
        __syncthreads();
        if (tid == 0) {
            float m = sred[0];
            for (int i = 1; i < 8; i++) m = fmaxf(m, sred[i]);
            sred[0] = m;
        }
        __syncthreads();
        mx = sred[0];
        __syncthreads();
        float s = 0.f;
#pragma unroll
        for (int q = 0; q < 4; q++)
            if (tid + q * 256 < Vsz) s += expf(lv[q] - mx);
#pragma unroll
        for (int o = 16; o > 0; o >>= 1) s += __shfl_xor_sync(0xffffffffu, s, o);
        if ((tid & 31) == 0) sred[tid >> 5] = s;
        __syncthreads();
        if (tid == 0) {
            float ss = 0.f;
            for (int i = 0; i < 8; i++) ss += sred[i];
            sred[0] = mx + logf(ss);
        }
        __syncthreads();
        float lse = sred[0];
        float* row = out + ((size_t)b * Tsz + tOut) * Vsz;
#pragma unroll
        for (int q = 0; q < 4; q++) {
            int i = tid + q * 256;
            if (i < Vsz) row[i] = lv[q] - lse;
        }
        return;
    }

    // week attention + cc build (256 threads)
    if (!doWeek) return;
    int b = bid - 512;
    for (int i = tid; i < Hsz; i += 256)
        su[i] = g_vgh[(size_t)b * NB + i] + g_vgh[VGH_STR + (size_t)b * NB + i];
    __syncthreads();
    int warp = tid >> 5, lane = tid & 31;
    for (int d = warp; d < NDAYS; d += 8) {
        const float* w = g_week + ((size_t)b * NDAYS + d) * Hsz;
        float p = 0.f;
        for (int h = lane; h < Hsz; h += 32) p += su[h] * w[h];
#pragma unroll
        for (int o = 16; o > 0; o >>= 1) p += __shfl_xor_sync(0xffffffffu, p, o);
        if (lane == 0) sc[d] = p;
    }
    __syncthreads();
    if (tid == 0) {
        float mx = -1e30f;
        for (int d = 0; d < NDAYS; d++) mx = fmaxf(mx, sc[d]);
        float e[NDAYS], s = 0.f;
        for (int d = 0; d < NDAYS; d++) { e[d] = expf(sc[d] - mx); s += e[d]; }
        for (int d = 0; d < NDAYS; d++) aw[d] = e[d] / s;
    }
    __syncthreads();
    for (int h = tid; h < Hsz; h += 256) {
        float c = 0.f;
#pragma unroll
        for (int d = 0; d < NDAYS; d++)
            c += aw[d] * g_week[((size_t)b * NDAYS + d) * Hsz + h];
        g_cc[(size_t)b * 2 * Hsz + Hsz + h] = c;
        g_cc[(size_t)b * 2 * Hsz + h] = hn[b * Hsz + h];
    }
}

__global__ void write_lastin_kernel(const int* __restrict__ label,
                                    float* __restrict__ out)
{
    int b = blockIdx.x * blockDim.x + threadIdx.x;
    if (b < Bsz)
        out[(size_t)Bsz * Tsz * Vsz + b] = (float)label[b * (Tsz + 1) + (Tsz - 1)];
}

// ---------------- host orchestration ----------------
static void launch_gemm(const float* A, const float* Bm, float* C,
                        int M, int N, int K, int transB, const float* bias,
                        int ldc, int splitZ, size_t splitStride)
{
    dim3 grid((N + BN - 1) / BN, (M + BM - 1) / BM, splitZ);
    tgemm<<<grid, 256>>>(A, Bm, C, M, N, K, transB, bias, ldc, splitStride);
}

extern "C" void kernel_launch(void* const* d_in, const int* in_sizes, int n_in,
                              void* d_out, int out_size)
{
    const float* enc_h   = (const float*)d_in[0];
    const float* enc_o   = (const float*)d_in[1];
    const int*   label   = (const int*)d_in[2];
    const int*   numpair = (const int*)d_in[3];
    const float* emb     = (const float*)d_in[4];
    const float* W_ih    = (const float*)d_in[5];
    const float* W_hh    = (const float*)d_in[6];
    const float* b_ih    = (const float*)d_in[7];
    const float* b_hh    = (const float*)d_in[8];
    const float* Wa      = (const float*)d_in[9];
    const float* wa_W    = (const float*)d_in[10];
    const float* fc_W    = (const float*)d_in[11];
    const float* fc_b    = (const float*)d_in[12];
    float* out = (float*)d_out;

    float *p_h, *p_vgh, *p_EW, *p_BigB, *p_P, *p_cc;
    cudaGetSymbolAddress((void**)&p_h,    g_h);
    cudaGetSymbolAddress((void**)&p_vgh,  g_vgh);
    cudaGetSymbolAddress((void**)&p_EW,   g_EW);
    cudaGetSymbolAddress((void**)&p_BigB, g_BigB);
    cudaGetSymbolAddress((void**)&p_P,    g_P);
    cudaGetSymbolAddress((void**)&p_cc,   g_cc);

    // h0 = encoder_hidden[0]
    cudaMemcpyAsync(p_h, enc_h, (size_t)Bsz * Hsz * sizeof(float),
                    cudaMemcpyDeviceToDevice);

    // one-time setup
    build_idx_kernel<<<(Tsz * Bsz + 255) / 256, 256>>>(label);
    build_bigB_kernel<<<(Hsz * NB + 255) / 256, 256>>>(Wa, W_hh);
    conv_bf16_kernel<<<(int)(((size_t)Bsz * Ssz * Hsz / 2 + 255) / 256), 256>>>(enc_o);
    // EW = emb @ W_ih^T + b_ih   [1000 x 1536]
    launch_gemm(emb, W_ih, p_EW, Vsz, H3, Esz, 1, b_ih, H3, 1, 0);

    // initial [v0 | gh0] = h0 @ [Wa | W_hh^T]  (split-K 2)
    launch_gemm(p_h, p_BigB, p_vgh, Bsz, NB, Hsz, 0, nullptr, NB, 2, VGH_STR);

    // pipelined main loop: 4 launches/step
    for (int t = 0; t < Tsz; t++) {
        float* hc = p_h + (size_t)(t & 1) * Bsz * Hsz;
        float* hn = p_h + (size_t)((t + 1) & 1) * Bsz * Hsz;
        int prev = (t > 0) ? 1 : 0;

        // L1: combine4(t-1) | gates(t) | day_attn(t)
        mega1_kernel<<<1024 + 1024 + Bsz * NDAYS, 256>>>(numpair, hc, hn, b_hh,
                                                         t, prev, 1);
        // L2: fcGEMM(t-1) | BigGEMM(t) ([u_t | gh_{t+1}], u_t = v_{t+1})
        mega2_kernel<<<512, 256>>>(hn, fc_W, prev, 1);
        // L3: fc_softmax(t-1) | week_attn(t)
        mega3_kernel<<<1024, 256>>>(fc_b, out, hn, t - 1, prev, 1);
        // L4: projGEMM(t): partials of cc @ wa_W^T (K=1024, split-K 4)
        launch_gemm(p_cc, wa_W, p_P, Bsz, Hsz, 2 * Hsz, 1, nullptr, Hsz,
                    4, BH);
    }

    // epilogue: flush tail of step T-1
    mega1_kernel<<<1024 + 1024 + Bsz * NDAYS, 256>>>(numpair, p_h, p_h, b_hh,
                                                     0, 1, 0);
    mega2_kernel<<<512, 256>>>(p_h, fc_W, 1, 0);
    mega3_kernel<<<1024, 256>>>(fc_b, out, p_h, Tsz - 1, 1, 0);

    if (out_size >= Bsz * Tsz * Vsz + Bsz)
        write_lastin_kernel<<<2, 256>>>(label, out);
}